// round 7
// baseline (speedup 1.0000x reference)
#include <cuda_runtime.h>
#include <cstdint>

#define N_EXP 16
#define MT_MAX 48
#define NTH 256
#define SA_ROWF 264                       // floats per A k-pair row (132 float2)
#define SA_FLOATS (16 * SA_ROWF)          // 4224
#define SB_ROWP 132                       // float2 per B k-pair row (128 + 4 pad)
#define SB_FLOATS (16 * SB_ROWP * 2)      // 4224
#define STG_FLOATS (SA_FLOATS + SB_FLOATS)
#define SMEM_BYTES (2 * STG_FLOATS * 4)   // 67584 B

// 8MB scratch: silu(g)*u activations [4096, 512]
__device__ float g_act[4096 * 512];

// rna-to-tf32: bump magnitude past truncation point (HW ignores low 13 bits)
__device__ __forceinline__ float frnd(float f) {
    return __uint_as_float(__float_as_uint(f) + 0x1000u);
}
__device__ __forceinline__ unsigned urnd(float f) {
    return __float_as_uint(f) + 0x1000u;
}

__device__ __forceinline__ void mma_tf32(float& d0, float& d1, float& d2, float& d3,
                                         unsigned a0, unsigned a1, unsigned a2, unsigned a3,
                                         unsigned b0, unsigned b1) {
    asm volatile(
        "mma.sync.aligned.m16n8k8.row.col.f32.tf32.tf32.f32 "
        "{%0,%1,%2,%3}, {%4,%5,%6,%7}, {%8,%9}, {%0,%1,%2,%3};\n"
        : "+f"(d0), "+f"(d1), "+f"(d2), "+f"(d3)
        : "r"(a0), "r"(a1), "r"(a2), "r"(a3), "r"(b0), "r"(b1));
}

// PASS2=0: gu GEMM. A=x[T,1024]; B cols interleaved (16-col g / u groups) so each
//          warp holds matching g,u accumulators; epilogue writes silu(g)*u -> g_act.
// PASS2=1: down GEMM. A=g_act[T,512]; B=down[e]; epilogue -> C.
template <int KDIM, int PASS2>
__global__ __launch_bounds__(NTH, 2)
void moe_gemm(const float* __restrict__ A, const float* __restrict__ Bw,
              const int* __restrict__ counts, float* __restrict__ C) {
    extern __shared__ float dsm[];
    const int tid = threadIdx.x;

    // ---- m-tile -> (expert, rows) ----
    int e = -1, m0 = 0, mEnd = 0;
    {
        int accT = 0, off = 0;
#pragma unroll
        for (int i = 0; i < N_EXP; i++) {
            int c = __ldg(counts + i);
            int nt = (c + 127) >> 7;
            if (e < 0 && (int)blockIdx.x < accT + nt) {
                e = i; m0 = off + (blockIdx.x - accT) * 128; mEnd = off + c;
            }
            accT += nt; off += c;
        }
    }
    if (e < 0) return;

    const int by = blockIdx.y;
    const int n0 = by * (PASS2 ? 128 : 64);
    const float* Ap = PASS2 ? (const float*)g_act : A;
    const float* Bp = Bw + (size_t)e * KDIM * 1024;
    const int LDA = PASS2 ? 512 : 1024;

    const int lane = tid & 31, w = tid >> 5;
    const int wm = w & 1, wn = w >> 1;        // warp tile: 64m x 32n
    const int g = lane >> 2, tg = lane & 3;
    const int a_mr = tid >> 3, a_j = tid & 7; // A producer: row, k-quad
    const int a_kk = a_j >> 1, a_q = a_j & 1;
    const int b_pr = tid >> 4, b_ch = tid & 15;              // B producer: pair-row, chunk
    const int b_klo = ((b_pr >> 2) << 3) + (b_pr & 3);       // k of pair low element

    float4 pa[4];   // A prefetch
    float4 pb[4];   // B prefetch: {lo,hi} x 2 chunks

    auto ldgA = [&](int t) {
#pragma unroll
        for (int p = 0; p < 4; p++) {
            int gm = m0 + a_mr + 32 * p;
            pa[p] = (gm < mEnd)
                ? *(const float4*)(Ap + (size_t)gm * LDA + t * 32 + a_j * 4)
                : make_float4(0.f, 0.f, 0.f, 0.f);
        }
    };
    auto ldgB = [&](int t) {
#pragma unroll
        for (int p = 0; p < 2; p++) {
            int c = b_ch + 16 * p;  // n-chunk 0..31 (4 floats each)
            int iext;
            if (PASS2) iext = n0 + 4 * c;
            else       iext = n0 + ((c >> 3) << 4) + ((c & 3) << 2) + (((c >> 2) & 1) << 9);
            const float* s = Bp + (size_t)(t * 32 + b_klo) * 1024 + iext;
            pb[2 * p]     = *(const float4*)s;              // row k
            pb[2 * p + 1] = *(const float4*)(s + 4 * 1024); // row k+4
        }
    };
    auto stsA = [&](int s) {
        float* sA = dsm + s * STG_FLOATS;
#pragma unroll
        for (int p = 0; p < 4; p++) {
            int m = a_mr + 32 * p;
            int mx = ((m ^ (a_kk << 3)) << 1) + a_q;
            float v[4] = {pa[p].x, pa[p].y, pa[p].z, pa[p].w};
#pragma unroll
            for (int c = 0; c < 4; c++)
                sA[(a_kk * 4 + c) * SA_ROWF + mx] = frnd(v[c]);
        }
    };
    auto stsB = [&](int s) {
        // interleaved pairs: sB2[pr][n] = (B[k][n], B[k+4][n]); rounding producer-side
        uint4* sB4 = (uint4*)(dsm + s * STG_FLOATS + SA_FLOATS);
#pragma unroll
        for (int p = 0; p < 2; p++) {
            int c = b_ch + 16 * p;
            float4 lo = pb[2 * p], hi = pb[2 * p + 1];
            uint4 w0 = make_uint4(urnd(lo.x), urnd(hi.x), urnd(lo.y), urnd(hi.y));
            uint4 w1 = make_uint4(urnd(lo.z), urnd(hi.z), urnd(lo.w), urnd(hi.w));
            // float2 index = b_pr*SB_ROWP + 4c  -> uint4 index = that/2
            int idx2 = b_pr * SB_ROWP + 4 * c;
            sB4[idx2 >> 1]       = w0;
            sB4[(idx2 >> 1) + 1] = w1;
        }
    };

    float acc4[4][4][4];
#pragma unroll
    for (int i = 0; i < 4; i++)
#pragma unroll
        for (int j = 0; j < 4; j++)
#pragma unroll
            for (int q = 0; q < 4; q++) acc4[i][j][q] = 0.f;

    auto compute = [&](int s) {
        const float2* sA2 = (const float2*)(dsm + s * STG_FLOATS);
        const float2* sB2 = (const float2*)(dsm + s * STG_FLOATS + SA_FLOATS);
#pragma unroll
        for (int ks = 0; ks < 4; ks++) {
            unsigned af[4][4], bf[4][2];
#pragma unroll
            for (int mf = 0; mf < 4; mf++) {
                int ml = wm * 64 + mf * 16 + g;
                int rb = (ks * 4 + tg) * 132;
                float2 lo = sA2[rb + (ml ^ (ks << 3))];
                float2 hi = sA2[rb + ((ml + 8) ^ (ks << 3))];
                af[mf][0] = __float_as_uint(lo.x);
                af[mf][1] = __float_as_uint(hi.x);
                af[mf][2] = __float_as_uint(lo.y);
                af[mf][3] = __float_as_uint(hi.y);
            }
#pragma unroll
            for (int nf = 0; nf < 4; nf++) {
                int nb = wn * 32 + nf * 8 + g;
                float2 b = sB2[(ks * 4 + tg) * SB_ROWP + nb];
                bf[nf][0] = __float_as_uint(b.x);
                bf[nf][1] = __float_as_uint(b.y);
            }
#pragma unroll
            for (int mf = 0; mf < 4; mf++)
#pragma unroll
                for (int nf = 0; nf < 4; nf++)
                    mma_tf32(acc4[mf][nf][0], acc4[mf][nf][1], acc4[mf][nf][2], acc4[mf][nf][3],
                             af[mf][0], af[mf][1], af[mf][2], af[mf][3],
                             bf[nf][0], bf[nf][1]);
        }
    };

    // ---- pipelined mainloop (2 stages, 1 sync per ktile) ----
    const int KT = KDIM / 32;
    ldgA(0); ldgB(0);
    stsA(0); stsB(0);
    __syncthreads();

    for (int t = 0; t < KT; t++) {
        int cur = t & 1, nxt = cur ^ 1;
        if (t + 1 < KT) { ldgA(t + 1); ldgB(t + 1); }
        compute(cur);
        if (t + 1 < KT) { stsA(nxt); stsB(nxt); }
        __syncthreads();
    }

    // ---- epilogue ----
    if (!PASS2) {
        // acc cols: nf 0..1 = g group, nf 2..3 = matching u group (same ext col)
#pragma unroll
        for (int mf = 0; mf < 4; mf++) {
#pragma unroll
            for (int nf = 0; nf < 2; nf++) {
                int row = m0 + wm * 64 + mf * 16 + g;
                int col = by * 64 + wn * 16 + nf * 8 + 2 * tg;
                if (row < mEnd) {
                    float g0 = acc4[mf][nf][0], g1 = acc4[mf][nf][1];
                    float u0 = acc4[mf][nf + 2][0], u1 = acc4[mf][nf + 2][1];
                    float2 v;
                    v.x = g0 / (1.f + __expf(-g0)) * u0;
                    v.y = g1 / (1.f + __expf(-g1)) * u1;
                    *(float2*)(g_act + (size_t)row * 512 + col) = v;
                }
                if (row + 8 < mEnd) {
                    float g0 = acc4[mf][nf][2], g1 = acc4[mf][nf][3];
                    float u0 = acc4[mf][nf + 2][2], u1 = acc4[mf][nf + 2][3];
                    float2 v;
                    v.x = g0 / (1.f + __expf(-g0)) * u0;
                    v.y = g1 / (1.f + __expf(-g1)) * u1;
                    *(float2*)(g_act + (size_t)(row + 8) * 512 + col) = v;
                }
            }
        }
    } else {
#pragma unroll
        for (int mf = 0; mf < 4; mf++) {
#pragma unroll
            for (int nf = 0; nf < 4; nf++) {
                int row = m0 + wm * 64 + mf * 16 + g;
                int col = n0 + wn * 32 + nf * 8 + 2 * tg;
                if (row < mEnd) {
                    float2 v = make_float2(acc4[mf][nf][0], acc4[mf][nf][1]);
                    *(float2*)(C + (size_t)row * 1024 + col) = v;
                }
                if (row + 8 < mEnd) {
                    float2 v = make_float2(acc4[mf][nf][2], acc4[mf][nf][3]);
                    *(float2*)(C + (size_t)(row + 8) * 1024 + col) = v;
                }
            }
        }
    }
}

extern "C" void kernel_launch(void* const* d_in, const int* in_sizes, int n_in,
                              void* d_out, int out_size) {
    const float* x    = (const float*)d_in[0];  // [4096, 1024]
    const float* gup  = (const float*)d_in[1];  // [16, 1024, 1024]
    const float* down = (const float*)d_in[2];  // [16, 512, 1024]
    const int* counts = (const int*)d_in[3];    // [16]
    float* out = (float*)d_out;                 // [4096, 1024]

    cudaFuncSetAttribute(moe_gemm<1024, 0>, cudaFuncAttributeMaxDynamicSharedMemorySize, SMEM_BYTES);
    cudaFuncSetAttribute(moe_gemm<512, 1>, cudaFuncAttributeMaxDynamicSharedMemorySize, SMEM_BYTES);

    moe_gemm<1024, 0><<<dim3(MT_MAX, 8), NTH, SMEM_BYTES>>>(x, gup, counts, nullptr);
    moe_gemm<512, 1><<<dim3(MT_MAX, 8), NTH, SMEM_BYTES>>>(nullptr, down, counts, out);
}

// round 8
// speedup vs baseline: 1.4558x; 1.4558x over previous
#include <cuda_runtime.h>
#include <cuda_fp16.h>
#include <cstdint>

#define N_EXP 16
#define MT_MAX 48
#define NTH 256
#define SA_ROWH 40                        // halves per A row (32 + 8 pad)
#define SA_FLOATS (128 * SA_ROWH / 2)     // 2560 floats = 5120 halves
#define SB_ROWF 132                       // floats per B row (128 + 4 pad)
#define SB_FLOATS (32 * SB_ROWF)          // 4224
#define STG_FLOATS (SA_FLOATS + SB_FLOATS)
#define SMEM_BYTES (2 * STG_FLOATS * 4)   // 54272 B

// 8MB scratch: silu(g)*u activations [4096, 512] (fp32)
__device__ float g_act[4096 * 512];

__device__ __forceinline__ unsigned pkh2(float hi, float lo) {
    unsigned d;
    asm("cvt.rn.f16x2.f32 %0, %1, %2;" : "=r"(d) : "f"(hi), "f"(lo));
    return d;
}

__device__ __forceinline__ void mma_f16(float& d0, float& d1, float& d2, float& d3,
                                        unsigned a0, unsigned a1, unsigned a2, unsigned a3,
                                        unsigned b0, unsigned b1) {
    asm volatile(
        "mma.sync.aligned.m16n8k16.row.col.f32.f16.f16.f32 "
        "{%0,%1,%2,%3}, {%4,%5,%6,%7}, {%8,%9}, {%0,%1,%2,%3};\n"
        : "+f"(d0), "+f"(d1), "+f"(d2), "+f"(d3)
        : "r"(a0), "r"(a1), "r"(a2), "r"(a3), "r"(b0), "r"(b1));
}

// PASS2=0: gu GEMM. A=x[T,1024]; B cols interleaved (16-col g / u groups) so each
//          warp holds matching g,u accumulators; epilogue writes silu(g)*u -> g_act.
// PASS2=1: down GEMM. A=g_act[T,512]; B=down[e]; epilogue -> C.
template <int KDIM, int PASS2>
__global__ __launch_bounds__(NTH, 2)
void moe_gemm(const float* __restrict__ A, const float* __restrict__ Bw,
              const int* __restrict__ counts, float* __restrict__ C) {
    extern __shared__ float dsm[];
    const int tid = threadIdx.x;

    // ---- m-tile -> (expert, rows) ----
    int e = -1, m0 = 0, mEnd = 0;
    {
        int accT = 0, off = 0;
#pragma unroll
        for (int i = 0; i < N_EXP; i++) {
            int c = __ldg(counts + i);
            int nt = (c + 127) >> 7;
            if (e < 0 && (int)blockIdx.x < accT + nt) {
                e = i; m0 = off + (blockIdx.x - accT) * 128; mEnd = off + c;
            }
            accT += nt; off += c;
        }
    }
    if (e < 0) return;

    const int by = blockIdx.y;
    const int n0 = by * (PASS2 ? 128 : 64);
    const float* Ap = PASS2 ? (const float*)g_act : A;
    const float* Bp = Bw + (size_t)e * KDIM * 1024;
    const int LDA = PASS2 ? 512 : 1024;

    const int lane = tid & 31, w = tid >> 5;
    const int wm = w & 1, wn = w >> 1;        // warp tile: 64m x 32n
    const int g = lane >> 2, tg = lane & 3;
    const int a_mr = tid >> 3, a_j = tid & 7; // A producer: row, k-quad
    const int b_k = tid >> 3, b_c = tid & 7;  // B producer: k-row, chunk

    float4 pa[4];  // A prefetch

    auto ldgA = [&](int t) {
#pragma unroll
        for (int p = 0; p < 4; p++) {
            int gm = m0 + a_mr + 32 * p;
            pa[p] = (gm < mEnd)
                ? *(const float4*)(Ap + (size_t)gm * LDA + t * 32 + a_j * 4)
                : make_float4(0.f, 0.f, 0.f, 0.f);
        }
    };
    auto stsA = [&](int s) {
        __half* sA = (__half*)(dsm + s * STG_FLOATS);
#pragma unroll
        for (int p = 0; p < 4; p++) {
            int m = a_mr + 32 * p;
            uint2 v;
            v.x = pkh2(pa[p].y, pa[p].x);  // halves k, k+1 (low = lower k)
            v.y = pkh2(pa[p].w, pa[p].z);  // halves k+2, k+3
            *(uint2*)(sA + m * SA_ROWH + 4 * a_j) = v;
        }
    };
    auto cpB = [&](int t, int s) {
        float* sB = dsm + s * STG_FLOATS + SA_FLOATS;
#pragma unroll
        for (int p = 0; p < 4; p++) {
            int nl = b_c + 8 * p;
            int iext;
            if (PASS2) iext = n0 + 4 * nl;
            else       iext = n0 + ((nl >> 3) << 4) + ((nl & 3) << 2) + (((nl >> 2) & 1) << 9);
            const float* src = Bp + (size_t)(t * 32 + b_k) * 1024 + iext;
            unsigned dst = (unsigned)__cvta_generic_to_shared(sB + b_k * SB_ROWF + 4 * nl);
            asm volatile("cp.async.cg.shared.global [%0], [%1], 16;" :: "r"(dst), "l"(src));
        }
    };

    float acc4[4][4][4];
#pragma unroll
    for (int i = 0; i < 4; i++)
#pragma unroll
        for (int j = 0; j < 4; j++)
#pragma unroll
            for (int q = 0; q < 4; q++) acc4[i][j][q] = 0.f;

    auto compute = [&](int s) {
        const __half* sA = (const __half*)(dsm + s * STG_FLOATS);
        const float* sB = dsm + s * STG_FLOATS + SA_FLOATS;
#pragma unroll
        for (int ks = 0; ks < 2; ks++) {  // two k16 steps cover BK=32
            const int klo = ks * 16;
            unsigned af[4][4], bf[4][2];
#pragma unroll
            for (int mf = 0; mf < 4; mf++) {
                int ml = wm * 64 + mf * 16 + g;
                const __half* r0 = sA + ml * SA_ROWH + klo + 2 * tg;
                af[mf][0] = *(const unsigned*)(r0);
                af[mf][1] = *(const unsigned*)(r0 + 8 * SA_ROWH);
                af[mf][2] = *(const unsigned*)(r0 + 8);
                af[mf][3] = *(const unsigned*)(r0 + 8 * SA_ROWH + 8);
            }
#pragma unroll
            for (int nf = 0; nf < 4; nf++) {
                int nb = wn * 32 + nf * 8 + g;
                const float* c0 = sB + (klo + 2 * tg) * SB_ROWF + nb;
                bf[nf][0] = pkh2(c0[SB_ROWF], c0[0]);           // k+1 (hi), k (lo)
                bf[nf][1] = pkh2(c0[9 * SB_ROWF], c0[8 * SB_ROWF]);
            }
#pragma unroll
            for (int mf = 0; mf < 4; mf++)
#pragma unroll
                for (int nf = 0; nf < 4; nf++)
                    mma_f16(acc4[mf][nf][0], acc4[mf][nf][1], acc4[mf][nf][2], acc4[mf][nf][3],
                            af[mf][0], af[mf][1], af[mf][2], af[mf][3],
                            bf[nf][0], bf[nf][1]);
        }
    };

    // ---- pipelined mainloop (2 stages, 1 sync per ktile) ----
    const int KT = KDIM / 32;
    ldgA(0);
    cpB(0, 0);
    asm volatile("cp.async.commit_group;");
    stsA(0);
    asm volatile("cp.async.wait_group 0;" ::: "memory");
    __syncthreads();

    for (int t = 0; t < KT; t++) {
        int cur = t & 1, nxt = cur ^ 1;
        if (t + 1 < KT) {
            ldgA(t + 1);
            cpB(t + 1, nxt);
            asm volatile("cp.async.commit_group;");
        }
        compute(cur);
        if (t + 1 < KT) {
            stsA(nxt);
            asm volatile("cp.async.wait_group 0;" ::: "memory");
        }
        __syncthreads();
    }

    // ---- epilogue ----
    if (!PASS2) {
        // acc cols: nf 0..1 = g group, nf 2..3 = matching u group (same ext col)
#pragma unroll
        for (int mf = 0; mf < 4; mf++) {
#pragma unroll
            for (int nf = 0; nf < 2; nf++) {
                int row = m0 + wm * 64 + mf * 16 + g;
                int col = by * 64 + wn * 16 + nf * 8 + 2 * tg;
                if (row < mEnd) {
                    float g0 = acc4[mf][nf][0], g1 = acc4[mf][nf][1];
                    float u0 = acc4[mf][nf + 2][0], u1 = acc4[mf][nf + 2][1];
                    float2 v;
                    v.x = g0 / (1.f + __expf(-g0)) * u0;
                    v.y = g1 / (1.f + __expf(-g1)) * u1;
                    *(float2*)(g_act + (size_t)row * 512 + col) = v;
                }
                if (row + 8 < mEnd) {
                    float g0 = acc4[mf][nf][2], g1 = acc4[mf][nf][3];
                    float u0 = acc4[mf][nf + 2][2], u1 = acc4[mf][nf + 2][3];
                    float2 v;
                    v.x = g0 / (1.f + __expf(-g0)) * u0;
                    v.y = g1 / (1.f + __expf(-g1)) * u1;
                    *(float2*)(g_act + (size_t)(row + 8) * 512 + col) = v;
                }
            }
        }
    } else {
#pragma unroll
        for (int mf = 0; mf < 4; mf++) {
#pragma unroll
            for (int nf = 0; nf < 4; nf++) {
                int row = m0 + wm * 64 + mf * 16 + g;
                int col = n0 + wn * 32 + nf * 8 + 2 * tg;
                if (row < mEnd) {
                    float2 v = make_float2(acc4[mf][nf][0], acc4[mf][nf][1]);
                    *(float2*)(C + (size_t)row * 1024 + col) = v;
                }
                if (row + 8 < mEnd) {
                    float2 v = make_float2(acc4[mf][nf][2], acc4[mf][nf][3]);
                    *(float2*)(C + (size_t)(row + 8) * 1024 + col) = v;
                }
            }
        }
    }
}

extern "C" void kernel_launch(void* const* d_in, const int* in_sizes, int n_in,
                              void* d_out, int out_size) {
    const float* x    = (const float*)d_in[0];  // [4096, 1024]
    const float* gup  = (const float*)d_in[1];  // [16, 1024, 1024]
    const float* down = (const float*)d_in[2];  // [16, 512, 1024]
    const int* counts = (const int*)d_in[3];    // [16]
    float* out = (float*)d_out;                 // [4096, 1024]

    cudaFuncSetAttribute(moe_gemm<1024, 0>, cudaFuncAttributeMaxDynamicSharedMemorySize, SMEM_BYTES);
    cudaFuncSetAttribute(moe_gemm<512, 1>, cudaFuncAttributeMaxDynamicSharedMemorySize, SMEM_BYTES);

    moe_gemm<1024, 0><<<dim3(MT_MAX, 8), NTH, SMEM_BYTES>>>(x, gup, counts, nullptr);
    moe_gemm<512, 1><<<dim3(MT_MAX, 8), NTH, SMEM_BYTES>>>(nullptr, down, counts, out);
}

// round 10
// speedup vs baseline: 1.5237x; 1.0467x over previous
#include <cuda_runtime.h>
#include <cuda_fp16.h>
#include <cstdint>

#define N_EXP 16
#define MT_MAX 48
#define NTH 256
#define SA_ROWH 40                       // halves per A row (32 + 8 pad) = 80B
#define SA_BYTES (128 * SA_ROWH * 2)     // 10240
#define SB_ROWW 136                      // words per B pair-row (128 + 8 pad)
#define SB_BYTES (16 * SB_ROWW * 4)      // 8704
#define STG_BYTES (SA_BYTES + SB_BYTES)  // 18944
#define SMEM_BYTES (2 * STG_BYTES)       // 37888

// fp16 scratches (+128 pad rows so unmasked tail tiles stay in-bounds; pads are
// never written and __device__ globals are zero-initialized -> deterministic)
__device__ __half g_xh[(4096 + 128) * 1024];
__device__ __half g_acth[(4096 + 128) * 512];

__device__ __forceinline__ unsigned pkh2(float hi, float lo) {
    unsigned d;
    asm("cvt.rn.f16x2.f32 %0, %1, %2;" : "=r"(d) : "f"(hi), "f"(lo));
    return d;
}

__global__ void cvt_x_kernel(const float* __restrict__ x) {
    unsigned id = blockIdx.x * blockDim.x + threadIdx.x;  // 2M half2
    float2 v = ((const float2*)x)[id];
    ((unsigned*)g_xh)[id] = pkh2(v.y, v.x);
}

__device__ __forceinline__ void mma_f16(float& d0, float& d1, float& d2, float& d3,
                                        unsigned a0, unsigned a1, unsigned a2, unsigned a3,
                                        unsigned b0, unsigned b1) {
    asm volatile(
        "mma.sync.aligned.m16n8k16.row.col.f32.f16.f16.f32 "
        "{%0,%1,%2,%3}, {%4,%5,%6,%7}, {%8,%9}, {%0,%1,%2,%3};\n"
        : "+f"(d0), "+f"(d1), "+f"(d2), "+f"(d3)
        : "r"(a0), "r"(a1), "r"(a2), "r"(a3), "r"(b0), "r"(b1));
}

// PASS2=0: gu GEMM. A=g_xh; B=gate_up[e], cols mapped so warp wn holds g cols
//          (nf 0..1) and matching u cols (nf 2..3); epilogue silu(g)*u -> g_acth (fp16).
// PASS2=1: down GEMM. A=g_acth; B=down[e]; epilogue fp32 -> C.
template <int KDIM, int PASS2>
__global__ __launch_bounds__(NTH, 2)
void moe_gemm(const float* __restrict__ Bw, const int* __restrict__ counts,
              float* __restrict__ C) {
    extern __shared__ char dsm[];
    const int tid = threadIdx.x;

    // ---- m-tile -> (expert, rows) ----
    int e = -1, m0 = 0, mEnd = 0;
    {
        int accT = 0, off = 0;
#pragma unroll
        for (int i = 0; i < N_EXP; i++) {
            int c = __ldg(counts + i);
            int nt = (c + 127) >> 7;
            if (e < 0 && (int)blockIdx.x < accT + nt) {
                e = i; m0 = off + (blockIdx.x - accT) * 128; mEnd = off + c;
            }
            accT += nt; off += c;
        }
    }
    if (e < 0) return;

    const int by = blockIdx.y;
    const int n0 = by * (PASS2 ? 128 : 64);
    const __half* Ah = PASS2 ? g_acth : g_xh;
    const int LDAh = PASS2 ? 512 : 1024;
    const float* Bp = Bw + (size_t)e * KDIM * 1024;

    const int lane = tid & 31, w = tid >> 5;
    const int wm = w & 1, wn = w >> 1;        // warp tile: 64m x 32n
    const int g = lane >> 2, tg = lane & 3;
    const int am = tid >> 1, ahc = tid & 1;   // A producer: row, half-of-row
    const int bp = tid >> 4, bc = tid & 15;   // B producer: pair-row, 8-col chunk
    const int bq = bc >> 2, br = bc & 3;
    int bcol;
    if (PASS2) bcol = n0 + bc * 8;
    else bcol = (br < 2) ? (n0 + bq * 16 + br * 8)
                         : (512 + n0 + bq * 16 + (br - 2) * 8);

    float4 pb[4];  // B prefetch: rows 2bp, 2bp+1 x 2 float4

    auto cpA = [&](int t, int s) {
        const __half* src = Ah + (size_t)(m0 + am) * LDAh + t * 32 + ahc * 16;
        unsigned d0 = (unsigned)__cvta_generic_to_shared(
            dsm + s * STG_BYTES + am * (SA_ROWH * 2) + ahc * 32);
        asm volatile("cp.async.cg.shared.global [%0], [%1], 16;" :: "r"(d0), "l"(src));
        asm volatile("cp.async.cg.shared.global [%0], [%1], 16;" :: "r"(d0 + 16), "l"(src + 8));
    };
    auto ldgB = [&](int t) {
        const float* s0 = Bp + (size_t)(t * 32 + 2 * bp) * 1024 + bcol;
        pb[0] = *(const float4*)s0;
        pb[1] = *(const float4*)(s0 + 4);
        pb[2] = *(const float4*)(s0 + 1024);
        pb[3] = *(const float4*)(s0 + 1028);
    };
    auto stsB = [&](int s) {
        // half2 pairs along k: (B[2p][n], B[2p+1][n]); swizzled word-in-chunk
        unsigned h[8];
#pragma unroll
        for (int i = 0; i < 4; i++) {
            h[i]     = pkh2((&pb[2].x)[i], (&pb[0].x)[i]);
            h[4 + i] = pkh2((&pb[3].x)[i], (&pb[1].x)[i]);
        }
        unsigned* sB = (unsigned*)(dsm + s * STG_BYTES + SA_BYTES);
        int wb = bp * SB_ROWW + 8 * bc;
#pragma unroll
        for (int j = 0; j < 4; j++)
            *(uint2*)(sB + wb + ((2 * j + 2 * bq) & 7)) =
                make_uint2(h[2 * j], h[2 * j + 1]);
    };

    float acc4[4][4][4];
#pragma unroll
    for (int i = 0; i < 4; i++)
#pragma unroll
        for (int j = 0; j < 4; j++)
#pragma unroll
            for (int q = 0; q < 4; q++) acc4[i][j][q] = 0.f;

    auto compute = [&](int s) {
        const __half* sA = (const __half*)(dsm + s * STG_BYTES);
        const unsigned* sB = (const unsigned*)(dsm + s * STG_BYTES + SA_BYTES);
#pragma unroll
        for (int ks = 0; ks < 2; ks++) {
            unsigned af[4][4], bf[4][2];
#pragma unroll
            for (int mf = 0; mf < 4; mf++) {
                int ml = wm * 64 + mf * 16 + g;
                const __half* r0 = sA + ml * SA_ROWH + ks * 16 + 2 * tg;
                af[mf][0] = *(const unsigned*)r0;
                af[mf][1] = *(const unsigned*)(r0 + 8 * SA_ROWH);
                af[mf][2] = *(const unsigned*)(r0 + 8);
                af[mf][3] = *(const unsigned*)(r0 + 8 * SA_ROWH + 8);
            }
#pragma unroll
            for (int nf = 0; nf < 4; nf++) {
                int wd = 8 * (4 * wn + nf) + ((g + 2 * wn) & 7);
                bf[nf][0] = sB[(ks * 8 + tg) * SB_ROWW + wd];
                bf[nf][1] = sB[(ks * 8 + tg + 4) * SB_ROWW + wd];
            }
#pragma unroll
            for (int mf = 0; mf < 4; mf++)
#pragma unroll
                for (int nf = 0; nf < 4; nf++)
                    mma_f16(acc4[mf][nf][0], acc4[mf][nf][1], acc4[mf][nf][2], acc4[mf][nf][3],
                            af[mf][0], af[mf][1], af[mf][2], af[mf][3],
                            bf[nf][0], bf[nf][1]);
        }
    };

    // ---- pipelined mainloop (2 stages, 1 sync per ktile) ----
    const int KT = KDIM / 32;
    cpA(0, 0);
    asm volatile("cp.async.commit_group;");
    ldgB(0);
    stsB(0);
    asm volatile("cp.async.wait_group 0;" ::: "memory");
    __syncthreads();

    for (int t = 0; t < KT; t++) {
        int cur = t & 1, nxt = cur ^ 1;
        if (t + 1 < KT) {
            cpA(t + 1, nxt);
            asm volatile("cp.async.commit_group;");
            ldgB(t + 1);
        }
        compute(cur);
        if (t + 1 < KT) {
            stsB(nxt);
            asm volatile("cp.async.wait_group 0;" ::: "memory");
        }
        __syncthreads();
    }

    // ---- epilogue ----
    if (!PASS2) {
        // nf 0..1 = g cols, nf 2..3 = matching u cols (same external col)
#pragma unroll
        for (int mf = 0; mf < 4; mf++) {
#pragma unroll
            for (int nf = 0; nf < 2; nf++) {
                int row = m0 + wm * 64 + mf * 16 + g;
                int col = by * 64 + wn * 16 + nf * 8 + 2 * tg;
                if (row < mEnd) {
                    float g0 = acc4[mf][nf][0], g1 = acc4[mf][nf][1];
                    float u0 = acc4[mf][nf + 2][0], u1 = acc4[mf][nf + 2][1];
                    float v0 = g0 / (1.f + __expf(-g0)) * u0;
                    float v1 = g1 / (1.f + __expf(-g1)) * u1;
                    *(unsigned*)(g_acth + (size_t)row * 512 + col) = pkh2(v1, v0);
                }
                if (row + 8 < mEnd) {
                    float g0 = acc4[mf][nf][2], g1 = acc4[mf][nf][3];
                    float u0 = acc4[mf][nf + 2][2], u1 = acc4[mf][nf + 2][3];
                    float v0 = g0 / (1.f + __expf(-g0)) * u0;
                    float v1 = g1 / (1.f + __expf(-g1)) * u1;
                    *(unsigned*)(g_acth + (size_t)(row + 8) * 512 + col) = pkh2(v1, v0);
                }
            }
        }
    } else {
#pragma unroll
        for (int mf = 0; mf < 4; mf++) {
#pragma unroll
            for (int nf = 0; nf < 4; nf++) {
                int row = m0 + wm * 64 + mf * 16 + g;
                int col = n0 + wn * 32 + nf * 8 + 2 * tg;
                if (row < mEnd) {
                    float2 v = make_float2(acc4[mf][nf][0], acc4[mf][nf][1]);
                    *(float2*)(C + (size_t)row * 1024 + col) = v;
                }
                if (row + 8 < mEnd) {
                    float2 v = make_float2(acc4[mf][nf][2], acc4[mf][nf][3]);
                    *(float2*)(C + (size_t)(row + 8) * 1024 + col) = v;
                }
            }
        }
    }
}

extern "C" void kernel_launch(void* const* d_in, const int* in_sizes, int n_in,
                              void* d_out, int out_size) {
    const float* x    = (const float*)d_in[0];  // [4096, 1024]
    const float* gup  = (const float*)d_in[1];  // [16, 1024, 1024]
    const float* down = (const float*)d_in[2];  // [16, 512, 1024]
    const int* counts = (const int*)d_in[3];    // [16]
    float* out = (float*)d_out;                 // [4096, 1024]

    cudaFuncSetAttribute(moe_gemm<1024, 0>, cudaFuncAttributeMaxDynamicSharedMemorySize, SMEM_BYTES);
    cudaFuncSetAttribute(moe_gemm<512, 1>, cudaFuncAttributeMaxDynamicSharedMemorySize, SMEM_BYTES);

    cvt_x_kernel<<<8192, 256>>>(x);
    moe_gemm<1024, 0><<<dim3(MT_MAX, 8), NTH, SMEM_BYTES>>>(gup, counts, nullptr);
    moe_gemm<512, 1><<<dim3(MT_MAX, 8), NTH, SMEM_BYTES>>>(down, counts, out);
}

// round 11
// speedup vs baseline: 1.5513x; 1.0181x over previous
#include <cuda_runtime.h>
#include <cuda_fp16.h>
#include <cstdint>

#define N_EXP 16
#define MT_MAX 48
#define NTH 256
#define SA_ROWH 40                       // halves per A row (32 + 8 pad) = 80B
#define SA_BYTES (128 * SA_ROWH * 2)     // 10240
#define SB_ROWW 136                      // words per B pair-row (128 + 8 pad)
#define SB_BYTES (16 * SB_ROWW * 4)      // 8704
#define STG_BYTES (SA_BYTES + SB_BYTES)  // 18944
#define SMEM_BYTES (2 * STG_BYTES)       // 37888

// fp16 scratches (+128 pad rows so unmasked tail tiles stay in-bounds; pads are
// never written and __device__ globals are zero-initialized -> deterministic)
__device__ __half g_xh[(4096 + 128) * 1024];
__device__ __half g_acth[(4096 + 128) * 512];

__device__ __forceinline__ unsigned pkh2(float hi, float lo) {
    unsigned d;
    asm("cvt.rn.f16x2.f32 %0, %1, %2;" : "=r"(d) : "f"(hi), "f"(lo));
    return d;
}

__global__ void cvt_x_kernel(const float4* __restrict__ x) {
    unsigned id = blockIdx.x * blockDim.x + threadIdx.x;  // 1M float4 = full x
    float4 v = x[id];
    ((uint2*)g_xh)[id] = make_uint2(pkh2(v.y, v.x), pkh2(v.w, v.z));
}

__device__ __forceinline__ void mma_f16(float& d0, float& d1, float& d2, float& d3,
                                        unsigned a0, unsigned a1, unsigned a2, unsigned a3,
                                        unsigned b0, unsigned b1) {
    asm volatile(
        "mma.sync.aligned.m16n8k16.row.col.f32.f16.f16.f32 "
        "{%0,%1,%2,%3}, {%4,%5,%6,%7}, {%8,%9}, {%0,%1,%2,%3};\n"
        : "+f"(d0), "+f"(d1), "+f"(d2), "+f"(d3)
        : "r"(a0), "r"(a1), "r"(a2), "r"(a3), "r"(b0), "r"(b1));
}

__device__ __forceinline__ void ldm_x4(unsigned* r, unsigned addr) {
    asm volatile("ldmatrix.sync.aligned.m8n8.x4.shared.b16 {%0,%1,%2,%3}, [%4];"
                 : "=r"(r[0]), "=r"(r[1]), "=r"(r[2]), "=r"(r[3]) : "r"(addr));
}

// PASS2=0: gu GEMM. A=g_xh; B=gate_up[e], cols mapped so warp wn holds g cols
//          (nf 0..1) and matching u cols (nf 2..3); epilogue silu(g)*u -> g_acth (fp16).
// PASS2=1: down GEMM. A=g_acth; B=down[e]; epilogue fp32 -> C.
template <int KDIM, int PASS2>
__global__ __launch_bounds__(NTH, 2)
void moe_gemm(const float* __restrict__ Bw, const int* __restrict__ counts,
              float* __restrict__ C) {
    extern __shared__ char dsm[];
    const int tid = threadIdx.x;

    // ---- m-tile -> (expert, rows) ----
    int e = -1, m0 = 0, mEnd = 0;
    {
        int accT = 0, off = 0;
#pragma unroll
        for (int i = 0; i < N_EXP; i++) {
            int c = __ldg(counts + i);
            int nt = (c + 127) >> 7;
            if (e < 0 && (int)blockIdx.x < accT + nt) {
                e = i; m0 = off + (blockIdx.x - accT) * 128; mEnd = off + c;
            }
            accT += nt; off += c;
        }
    }
    if (e < 0) return;

    const int by = blockIdx.y;
    const int n0 = by * (PASS2 ? 128 : 64);
    const __half* Ah = PASS2 ? g_acth : g_xh;
    const int LDAh = PASS2 ? 512 : 1024;
    const float* Bp = Bw + (size_t)e * KDIM * 1024;

    const int lane = tid & 31, w = tid >> 5;
    const int wm = w & 1, wn = w >> 1;        // warp tile: 64m x 32n
    const int g = lane >> 2, tg = lane & 3;
    const int am = tid >> 1, ahc = tid & 1;   // A producer: row, half-of-row
    const int bp = tid >> 4, bc = tid & 15;   // B producer: pair-row, 8-col chunk
    const int bq = bc >> 2, br = bc & 3;
    int bcol;
    if (PASS2) bcol = n0 + bc * 8;
    else bcol = (br < 2) ? (n0 + bq * 16 + br * 8)
                         : (512 + n0 + bq * 16 + (br - 2) * 8);

    // ldmatrix lane address pattern: matrix j <- addresses of lanes 8j..8j+7.
    // m0: rows +0..7 k+0..7 | m1: rows +8..15 k+0..7 | m2: rows +0..7 k+8..15
    // | m3: rows +8..15 k+8..15  => af[0..3] identical to scalar-LDS layout.
    const int a_lrow = wm * 64 + (lane & 7) + 8 * ((lane >> 3) & 1);
    const int a_lcol = 8 * (lane >> 4);  // halves

    float4 pb[4];  // B prefetch: rows 2bp, 2bp+1 x 2 float4

    auto cpA = [&](int t, int s) {
        const __half* src = Ah + (size_t)(m0 + am) * LDAh + t * 32 + ahc * 16;
        unsigned d0 = (unsigned)__cvta_generic_to_shared(
            dsm + s * STG_BYTES + am * (SA_ROWH * 2) + ahc * 32);
        asm volatile("cp.async.cg.shared.global [%0], [%1], 16;" :: "r"(d0), "l"(src));
        asm volatile("cp.async.cg.shared.global [%0], [%1], 16;" :: "r"(d0 + 16), "l"(src + 8));
    };
    auto ldgB = [&](int t) {
        const float* s0 = Bp + (size_t)(t * 32 + 2 * bp) * 1024 + bcol;
        pb[0] = *(const float4*)s0;
        pb[1] = *(const float4*)(s0 + 4);
        pb[2] = *(const float4*)(s0 + 1024);
        pb[3] = *(const float4*)(s0 + 1028);
    };
    auto stsB = [&](int s) {
        // half2 pairs along k: (B[2p][n], B[2p+1][n]); swizzled word-in-chunk
        unsigned h[8];
#pragma unroll
        for (int i = 0; i < 4; i++) {
            h[i]     = pkh2((&pb[2].x)[i], (&pb[0].x)[i]);
            h[4 + i] = pkh2((&pb[3].x)[i], (&pb[1].x)[i]);
        }
        unsigned* sB = (unsigned*)(dsm + s * STG_BYTES + SA_BYTES);
        int wb = bp * SB_ROWW + 8 * bc;
#pragma unroll
        for (int j = 0; j < 4; j++)
            *(uint2*)(sB + wb + ((2 * j + 2 * bq) & 7)) =
                make_uint2(h[2 * j], h[2 * j + 1]);
    };

    float acc4[4][4][4];
#pragma unroll
    for (int i = 0; i < 4; i++)
#pragma unroll
        for (int j = 0; j < 4; j++)
#pragma unroll
            for (int q = 0; q < 4; q++) acc4[i][j][q] = 0.f;

    auto compute = [&](int s) {
        const unsigned abase = (unsigned)__cvta_generic_to_shared(dsm + s * STG_BYTES) +
                               (a_lrow * SA_ROWH + a_lcol) * 2;
        const unsigned* sB = (const unsigned*)(dsm + s * STG_BYTES + SA_BYTES);
        // batched B fragment loads for both ks steps (latency overlaps ks=0 MMAs)
        unsigned bf[2][4][2];
#pragma unroll
        for (int ks = 0; ks < 2; ks++)
#pragma unroll
            for (int nf = 0; nf < 4; nf++) {
                int wd = 8 * (4 * wn + nf) + ((g + 2 * wn) & 7);
                bf[ks][nf][0] = sB[(ks * 8 + tg) * SB_ROWW + wd];
                bf[ks][nf][1] = sB[(ks * 8 + tg + 4) * SB_ROWW + wd];
            }
#pragma unroll
        for (int ks = 0; ks < 2; ks++) {
            unsigned af[4][4];
#pragma unroll
            for (int mf = 0; mf < 4; mf++)
                ldm_x4(af[mf], abase + mf * (16 * SA_ROWH * 2) + ks * 32);
#pragma unroll
            for (int mf = 0; mf < 4; mf++)
#pragma unroll
                for (int nf = 0; nf < 4; nf++)
                    mma_f16(acc4[mf][nf][0], acc4[mf][nf][1], acc4[mf][nf][2], acc4[mf][nf][3],
                            af[mf][0], af[mf][1], af[mf][2], af[mf][3],
                            bf[ks][nf][0], bf[ks][nf][1]);
        }
    };

    // ---- pipelined mainloop (2 stages, 1 sync per ktile) ----
    const int KT = KDIM / 32;
    cpA(0, 0);
    asm volatile("cp.async.commit_group;");
    ldgB(0);
    stsB(0);
    asm volatile("cp.async.wait_group 0;" ::: "memory");
    __syncthreads();

    for (int t = 0; t < KT; t++) {
        int cur = t & 1, nxt = cur ^ 1;
        if (t + 1 < KT) {
            cpA(t + 1, nxt);
            asm volatile("cp.async.commit_group;");
            ldgB(t + 1);
        }
        compute(cur);
        if (t + 1 < KT) {
            stsB(nxt);
            asm volatile("cp.async.wait_group 0;" ::: "memory");
        }
        __syncthreads();
    }

    // ---- epilogue ----
    if (!PASS2) {
        // nf 0..1 = g cols, nf 2..3 = matching u cols (same external col)
#pragma unroll
        for (int mf = 0; mf < 4; mf++) {
#pragma unroll
            for (int nf = 0; nf < 2; nf++) {
                int row = m0 + wm * 64 + mf * 16 + g;
                int col = by * 64 + wn * 16 + nf * 8 + 2 * tg;
                if (row < mEnd) {
                    float g0 = acc4[mf][nf][0], g1 = acc4[mf][nf][1];
                    float u0 = acc4[mf][nf + 2][0], u1 = acc4[mf][nf + 2][1];
                    float v0 = g0 / (1.f + __expf(-g0)) * u0;
                    float v1 = g1 / (1.f + __expf(-g1)) * u1;
                    *(unsigned*)(g_acth + (size_t)row * 512 + col) = pkh2(v1, v0);
                }
                if (row + 8 < mEnd) {
                    float g0 = acc4[mf][nf][2], g1 = acc4[mf][nf][3];
                    float u0 = acc4[mf][nf + 2][2], u1 = acc4[mf][nf + 2][3];
                    float v0 = g0 / (1.f + __expf(-g0)) * u0;
                    float v1 = g1 / (1.f + __expf(-g1)) * u1;
                    *(unsigned*)(g_acth + (size_t)(row + 8) * 512 + col) = pkh2(v1, v0);
                }
            }
        }
    } else {
#pragma unroll
        for (int mf = 0; mf < 4; mf++) {
#pragma unroll
            for (int nf = 0; nf < 4; nf++) {
                int row = m0 + wm * 64 + mf * 16 + g;
                int col = n0 + wn * 32 + nf * 8 + 2 * tg;
                if (row < mEnd) {
                    float2 v = make_float2(acc4[mf][nf][0], acc4[mf][nf][1]);
                    *(float2*)(C + (size_t)row * 1024 + col) = v;
                }
                if (row + 8 < mEnd) {
                    float2 v = make_float2(acc4[mf][nf][2], acc4[mf][nf][3]);
                    *(float2*)(C + (size_t)(row + 8) * 1024 + col) = v;
                }
            }
        }
    }
}

extern "C" void kernel_launch(void* const* d_in, const int* in_sizes, int n_in,
                              void* d_out, int out_size) {
    const float* x    = (const float*)d_in[0];  // [4096, 1024]
    const float* gup  = (const float*)d_in[1];  // [16, 1024, 1024]
    const float* down = (const float*)d_in[2];  // [16, 512, 1024]
    const int* counts = (const int*)d_in[3];    // [16]
    float* out = (float*)d_out;                 // [4096, 1024]

    cudaFuncSetAttribute(moe_gemm<1024, 0>, cudaFuncAttributeMaxDynamicSharedMemorySize, SMEM_BYTES);
    cudaFuncSetAttribute(moe_gemm<512, 1>, cudaFuncAttributeMaxDynamicSharedMemorySize, SMEM_BYTES);

    cvt_x_kernel<<<4096, 256>>>((const float4*)x);
    moe_gemm<1024, 0><<<dim3(MT_MAX, 8), NTH, SMEM_BYTES>>>(gup, counts, nullptr);
    moe_gemm<512, 1><<<dim3(MT_MAX, 8), NTH, SMEM_BYTES>>>(down, counts, out);
}